// round 5
// baseline (speedup 1.0000x reference)
#include <cuda_runtime.h>
#include <cstdint>
#include <math.h>

// ---------------------------------------------------------------------------
// Energy_Layer via tf32 mma.sync (m16n8k8), fragment-major smem layouts.
//  out = sum_e [ relu(tanh((p1[src]+p2[dst])@U0^T+b0)@U1^T+b1) . km[src] + kb[src] ]
//  km  = h2 @ M + bc,  kb = h2 . v + c,  M = K2W^T U2W, ...
//
// Fragment-major layouts (written by us, read as whole fragments):
//  A:  block (mb = r>>4, kb = k>>3), bi = mb*16+kb, stride 132 floats.
//      addr = bi*132 + ((r&7)*4 + (k&3))*4 + ((r>>3)&1) + (((k>>2)&1)<<1)
//      -> per-lane LDS.128 yields {a0,a1,a2,a3}.
//  W:  block (kb = k>>3, nb = n>>3), bi = kb*16+nb, stride 68 floats.
//      addr = bi*68 + ((n&7)*4 + (k&3))*2 + ((k>>2)&1)
//      -> per-lane LDS.64 yields {b0,b1}.
// ---------------------------------------------------------------------------

#define N_NODES 50000
#define N_EDGES 500000
#define DIM     128
#define GRID_P  152
#define NTHR    512

#define A_BS 132
#define W_BS 68

// smem layout in floats
#define F_B1  0
#define F_B2  128
#define F_V   256
#define F_KB  384
#define F_RED 512
#define F_W1  544
#define F_W2  (F_W1 + 256 * W_BS)
#define F_AS  (F_W2 + 256 * W_BS)
#define SMEM_TOTAL ((F_AS + 128 * A_BS) * 4)   // 209024 bytes

// device scratch
__device__ float g_h1[(size_t)N_NODES * DIM];
__device__ float g_p1[(size_t)N_NODES * DIM];
__device__ float g_p2[(size_t)N_NODES * DIM];
__device__ float g_agg[(size_t)N_NODES * DIM];
__device__ float g_t[(size_t)N_NODES * DIM];
__device__ float g_km[(size_t)N_NODES * DIM];
__device__ float g_kb[N_NODES];
__device__ float g_M[DIM * DIM];
__device__ float g_bc[DIM];
__device__ float g_v[DIM];
__device__ float g_c[1];

// ---------------------------------------------------------------------------
__device__ __forceinline__ float tf32r(float x) {
    uint32_t u;
    asm("cvt.rna.tf32.f32 %0, %1;" : "=r"(u) : "f"(x));
    return __uint_as_float(u);
}

__device__ __forceinline__ void mma_tf32(float* c4, float a0, float a1,
                                         float a2, float a3, float b0, float b1) {
    asm volatile(
        "mma.sync.aligned.m16n8k8.row.col.f32.tf32.tf32.f32 "
        "{%0,%1,%2,%3},{%4,%5,%6,%7},{%8,%9},{%0,%1,%2,%3};"
        : "+f"(c4[0]), "+f"(c4[1]), "+f"(c4[2]), "+f"(c4[3])
        : "r"(__float_as_uint(a0)), "r"(__float_as_uint(a1)),
          "r"(__float_as_uint(a2)), "r"(__float_as_uint(a3)),
          "r"(__float_as_uint(b0)), "r"(__float_as_uint(b1)));
}

// fragment address helpers (float offsets)
__device__ __forceinline__ int a_addr(int r, int c) {
    return ((r >> 4) * 16 + (c >> 3)) * A_BS + ((r & 7) * 4 + (c & 3)) * 4 +
           ((r >> 3) & 1) + (((c >> 2) & 1) << 1);
}

// ---------------------------------------------------------------------------
// W^T fragment loader: Ws holds B[k][n] = W[n][k].
// warp spans 32 n-rows, fixed k-quad -> 2-way store conflicts max.
__device__ __forceinline__ void load_W(float* Ws, const float* __restrict__ W,
                                       int tid) {
#pragma unroll
    for (int i = 0; i < 8; i++) {
        int pos = i * NTHR + tid;
        int n = pos & 127, kq = pos >> 7;           // k = kq*4 + j
        float4 w = *(const float4*)(W + n * DIM + kq * 4);
        int base = ((kq >> 1) * 16 + (n >> 3)) * W_BS + ((n & 7) * 4) * 2 +
                   (kq & 1);
        Ws[base + 0] = tf32r(w.x);
        Ws[base + 2] = tf32r(w.y);
        Ws[base + 4] = tf32r(w.z);
        Ws[base + 6] = tf32r(w.w);
    }
}

// row-major source: Ws holds B[k][n] = W[k][n] (for fused matrix M).
// warp spans 32 k-rows, fixed n-quad.
__device__ __forceinline__ void load_W_rows(float* Ws,
                                            const float* __restrict__ W, int tid) {
#pragma unroll
    for (int i = 0; i < 8; i++) {
        int pos = i * NTHR + tid;
        int k = pos & 127, q = pos >> 7;            // n = q*4 + j
        float4 w = *(const float4*)(W + k * DIM + q * 4);
        int base = ((k >> 3) * 16 + (q >> 1)) * W_BS + (k & 3) * 2 +
                   ((k >> 2) & 1) + ((q & 1) * 4) * 8;
        Ws[base + 0 * 8] = tf32r(w.x);
        Ws[base + 1 * 8] = tf32r(w.y);
        Ws[base + 2 * 8] = tf32r(w.z);
        Ws[base + 3 * 8] = tf32r(w.w);
    }
}

// A tile fragment loader (row r per warp, 32 k-quads across lanes)
__device__ __forceinline__ void load_A(float* As, const float* __restrict__ A,
                                       int row0, int M, int tid) {
#pragma unroll
    for (int i = 0; i < 8; i++) {
        int idx = i * NTHR + tid;
        int r = idx >> 5, q = idx & 31;
        int row = row0 + r;
        float4 v = make_float4(0.f, 0.f, 0.f, 0.f);
        if (row < M) v = *(const float4*)(A + (size_t)row * DIM + q * 4);
        int base = ((r >> 4) * 16 + (q >> 1)) * A_BS + ((r & 7) * 4) * 4 +
                   ((r >> 3) & 1) + ((q & 1) << 1);
        As[base + 0] = tf32r(v.x);
        As[base + 4] = tf32r(v.y);
        As[base + 8] = tf32r(v.z);
        As[base + 12] = tf32r(v.w);
    }
}

__device__ __forceinline__ void load_A_gather(float* As,
                                              const int* __restrict__ src,
                                              const int* __restrict__ dst,
                                              const float* __restrict__ P1,
                                              const float* __restrict__ P2,
                                              int row0, int M, int tid) {
#pragma unroll
    for (int i = 0; i < 8; i++) {
        int idx = i * NTHR + tid;
        int r = idx >> 5, q = idx & 31;
        int row = row0 + r;
        float4 v = make_float4(0.f, 0.f, 0.f, 0.f);
        if (row < M) {
            int s = __ldg(src + row);
            int d = __ldg(dst + row);
            float4 a = *(const float4*)(P1 + (size_t)s * DIM + q * 4);
            float4 b = *(const float4*)(P2 + (size_t)d * DIM + q * 4);
            v = make_float4(a.x + b.x, a.y + b.y, a.z + b.z, a.w + b.w);
        }
        int base = ((r >> 4) * 16 + (q >> 1)) * A_BS + ((r & 7) * 4) * 4 +
                   ((r >> 3) & 1) + ((q & 1) << 1);
        As[base + 0] = tf32r(v.x);
        As[base + 4] = tf32r(v.y);
        As[base + 8] = tf32r(v.z);
        As[base + 12] = tf32r(v.w);
    }
}

// 128x128x128: 16 warps, warp tile 32x32 (mt=2, nt=4), fragment loads
__device__ __forceinline__ void gemm128(const float* Af, const float* Wf,
                                        float acc[2][4][4], int mb0, int nb0,
                                        int lane) {
    const float* ap = Af + mb0 * 16 * A_BS + lane * 4;
    const float* wp = Wf + nb0 * W_BS + lane * 2;
#pragma unroll
    for (int kk = 0; kk < 16; kk++) {
        float4 a0 = *(const float4*)(ap + kk * A_BS);
        float4 a1 = *(const float4*)(ap + (16 + kk) * A_BS);
        float2 b0 = *(const float2*)(wp + (kk * 16 + 0) * W_BS);
        float2 b1 = *(const float2*)(wp + (kk * 16 + 1) * W_BS);
        float2 b2 = *(const float2*)(wp + (kk * 16 + 2) * W_BS);
        float2 b3 = *(const float2*)(wp + (kk * 16 + 3) * W_BS);
        mma_tf32(acc[0][0], a0.x, a0.y, a0.z, a0.w, b0.x, b0.y);
        mma_tf32(acc[1][0], a1.x, a1.y, a1.z, a1.w, b0.x, b0.y);
        mma_tf32(acc[0][1], a0.x, a0.y, a0.z, a0.w, b1.x, b1.y);
        mma_tf32(acc[1][1], a1.x, a1.y, a1.z, a1.w, b1.x, b1.y);
        mma_tf32(acc[0][2], a0.x, a0.y, a0.z, a0.w, b2.x, b2.y);
        mma_tf32(acc[1][2], a1.x, a1.y, a1.z, a1.w, b2.x, b2.y);
        mma_tf32(acc[0][3], a0.x, a0.y, a0.z, a0.w, b3.x, b3.y);
        mma_tf32(acc[1][3], a1.x, a1.y, a1.z, a1.w, b3.x, b3.y);
    }
}

#define ZERO_ACC(acc)                                   \
    _Pragma("unroll") for (int _m = 0; _m < 2; _m++)    \
    _Pragma("unroll") for (int _n = 0; _n < 4; _n++)    \
    _Pragma("unroll") for (int _j = 0; _j < 4; _j++) acc[_m][_n][_j] = 0.f;

// ---------------------------------------------------------------------------
// SINGLE gemm: C = act(A@W^T + b)     ACT: 0 none, 1 tanh
template <int ACT>
__global__ void __launch_bounds__(NTHR, 1)
k_single(const float* __restrict__ A, const float* __restrict__ W,
         const float* __restrict__ bias, float* __restrict__ C, int M) {
    extern __shared__ float sm[];
    float *B1 = sm + F_B1, *W1 = sm + F_W1, *As = sm + F_AS;
    const int tid = threadIdx.x;
    if (tid < 128) B1[tid] = __ldg(bias + tid);
    load_W(W1, W, tid);

    const int wid = tid >> 5, lane = tid & 31;
    const int gr = lane >> 2, tg = lane & 3;
    const int R0 = (wid >> 2) * 32, C0 = (wid & 3) * 32;
    const int mb0 = (wid >> 2) * 2, nb0 = (wid & 3) * 4;
    const int tiles = (M + 127) >> 7;

    for (int tile = blockIdx.x; tile < tiles; tile += gridDim.x) {
        const int row0 = tile << 7;
        __syncthreads();
        load_A(As, A, row0, M, tid);
        __syncthreads();
        float acc[2][4][4];
        ZERO_ACC(acc);
        gemm128(As, W1, acc, mb0, nb0, lane);
#pragma unroll
        for (int mt = 0; mt < 2; mt++) {
            int rl0 = R0 + mt * 16 + gr, rl1 = rl0 + 8;
#pragma unroll
            for (int nt = 0; nt < 4; nt++) {
                int c0 = C0 + nt * 8 + 2 * tg;
                float b0 = B1[c0], b1 = B1[c0 + 1];
                float v00 = acc[mt][nt][0] + b0, v01 = acc[mt][nt][1] + b1;
                float v10 = acc[mt][nt][2] + b0, v11 = acc[mt][nt][3] + b1;
                if (ACT == 1) { v00 = tanhf(v00); v01 = tanhf(v01);
                                v10 = tanhf(v10); v11 = tanhf(v11); }
                if (row0 + rl0 < M)
                    *(float2*)(C + (size_t)(row0 + rl0) * DIM + c0) =
                        make_float2(v00, v01);
                if (row0 + rl1 < M)
                    *(float2*)(C + (size_t)(row0 + rl1) * DIM + c0) =
                        make_float2(v10, v11);
            }
        }
    }
}

// ---------------------------------------------------------------------------
// DUAL gemm: C1 = A@Wa^T + ba ; C2 = A@Wb^T + bb
__global__ void __launch_bounds__(NTHR, 1)
k_dual(const float* __restrict__ A, const float* __restrict__ Wa,
       const float* __restrict__ ba, const float* __restrict__ Wb,
       const float* __restrict__ bb, float* __restrict__ C1,
       float* __restrict__ C2, int M) {
    extern __shared__ float sm[];
    float *B1 = sm + F_B1, *B2 = sm + F_B2;
    float *W1 = sm + F_W1, *W2 = sm + F_W2, *As = sm + F_AS;
    const int tid = threadIdx.x;
    if (tid < 128) { B1[tid] = __ldg(ba + tid); B2[tid] = __ldg(bb + tid); }
    load_W(W1, Wa, tid);
    load_W(W2, Wb, tid);

    const int wid = tid >> 5, lane = tid & 31;
    const int gr = lane >> 2, tg = lane & 3;
    const int R0 = (wid >> 2) * 32, C0 = (wid & 3) * 32;
    const int mb0 = (wid >> 2) * 2, nb0 = (wid & 3) * 4;
    const int tiles = (M + 127) >> 7;

    for (int tile = blockIdx.x; tile < tiles; tile += gridDim.x) {
        const int row0 = tile << 7;
        __syncthreads();
        load_A(As, A, row0, M, tid);
        __syncthreads();
#pragma unroll
        for (int pass = 0; pass < 2; pass++) {
            const float* Ws = pass ? W2 : W1;
            const float* Bs = pass ? B2 : B1;
            float* C = pass ? C2 : C1;
            float acc[2][4][4];
            ZERO_ACC(acc);
            gemm128(As, Ws, acc, mb0, nb0, lane);
#pragma unroll
            for (int mt = 0; mt < 2; mt++) {
                int rl0 = R0 + mt * 16 + gr, rl1 = rl0 + 8;
#pragma unroll
                for (int nt = 0; nt < 4; nt++) {
                    int c0 = C0 + nt * 8 + 2 * tg;
                    float b0 = Bs[c0], b1 = Bs[c0 + 1];
                    if (row0 + rl0 < M)
                        *(float2*)(C + (size_t)(row0 + rl0) * DIM + c0) =
                            make_float2(acc[mt][nt][0] + b0, acc[mt][nt][1] + b1);
                    if (row0 + rl1 < M)
                        *(float2*)(C + (size_t)(row0 + rl1) * DIM + c0) =
                            make_float2(acc[mt][nt][2] + b0, acc[mt][nt][3] + b1);
                }
            }
        }
    }
}

// ---------------------------------------------------------------------------
// NODECHAIN:  h2 = relu(t@K1^T + K1b);  km = h2@M + bc;  kb = h2.v + c
__global__ void __launch_bounds__(NTHR, 1)
k_nodechain(const float* __restrict__ T, const float* __restrict__ K1W,
            const float* __restrict__ K1b, const float* __restrict__ Mw,
            const float* __restrict__ bc, const float* __restrict__ vv,
            const float* __restrict__ cc, float* __restrict__ km,
            float* __restrict__ kb, int M) {
    extern __shared__ float sm[];
    float *B1 = sm + F_B1, *B2 = sm + F_B2, *V = sm + F_V, *KBs = sm + F_KB;
    float *W1 = sm + F_W1, *W2 = sm + F_W2, *As = sm + F_AS;
    const int tid = threadIdx.x;
    if (tid < 128) { B1[tid] = __ldg(K1b + tid); B2[tid] = __ldg(bc + tid);
                     V[tid] = __ldg(vv + tid); }
    const float cval = __ldg(cc);
    load_W(W1, K1W, tid);
    load_W_rows(W2, Mw, tid);

    const int wid = tid >> 5, lane = tid & 31;
    const int gr = lane >> 2, tg = lane & 3;
    const int R0 = (wid >> 2) * 32, C0 = (wid & 3) * 32;
    const int mb0 = (wid >> 2) * 2, nb0 = (wid & 3) * 4;
    const int tiles = (M + 127) >> 7;

    for (int tile = blockIdx.x; tile < tiles; tile += gridDim.x) {
        const int row0 = tile << 7;
        __syncthreads();
        load_A(As, T, row0, M, tid);
        __syncthreads();
        float acc[2][4][4];
        ZERO_ACC(acc);
        gemm128(As, W1, acc, mb0, nb0, lane);
        __syncthreads();
        // h2 = relu(acc + b1) -> As fragment layout; zero kb accumulators
        if (tid < 128) KBs[tid] = 0.f;
#pragma unroll
        for (int mt = 0; mt < 2; mt++) {
            int rl0 = R0 + mt * 16 + gr;
#pragma unroll
            for (int nt = 0; nt < 4; nt++) {
                int c0 = C0 + nt * 8 + 2 * tg;
                float b0 = B1[c0], b1 = B1[c0 + 1];
                int base = a_addr(rl0, c0);
                As[base + 0] = tf32r(fmaxf(acc[mt][nt][0] + b0, 0.f));
                As[base + 4] = tf32r(fmaxf(acc[mt][nt][1] + b1, 0.f));
                As[base + 1] = tf32r(fmaxf(acc[mt][nt][2] + b0, 0.f));
                As[base + 5] = tf32r(fmaxf(acc[mt][nt][3] + b1, 0.f));
            }
        }
        __syncthreads();
        // kb partials from accumulators (pre-round values)
#pragma unroll
        for (int mt = 0; mt < 2; mt++) {
            int rl0 = R0 + mt * 16 + gr;
            float p0 = 0.f, p1 = 0.f;
#pragma unroll
            for (int nt = 0; nt < 4; nt++) {
                int c0 = C0 + nt * 8 + 2 * tg;
                float b0 = B1[c0], b1 = B1[c0 + 1];
                p0 = fmaf(fmaxf(acc[mt][nt][0] + b0, 0.f), V[c0], p0);
                p0 = fmaf(fmaxf(acc[mt][nt][1] + b1, 0.f), V[c0 + 1], p0);
                p1 = fmaf(fmaxf(acc[mt][nt][2] + b0, 0.f), V[c0], p1);
                p1 = fmaf(fmaxf(acc[mt][nt][3] + b1, 0.f), V[c0 + 1], p1);
            }
            atomicAdd(KBs + rl0, p0);
            atomicAdd(KBs + rl0 + 8, p1);
        }
        // km = h2 @ M + bc
        ZERO_ACC(acc);
        gemm128(As, W2, acc, mb0, nb0, lane);
        __syncthreads();   // atomics done + As reads done
        if (tid < 128 && row0 + tid < M) kb[row0 + tid] = KBs[tid] + cval;
#pragma unroll
        for (int mt = 0; mt < 2; mt++) {
            int rl0 = R0 + mt * 16 + gr, rl1 = rl0 + 8;
#pragma unroll
            for (int nt = 0; nt < 4; nt++) {
                int c0 = C0 + nt * 8 + 2 * tg;
                float b0 = B2[c0], b1 = B2[c0 + 1];
                if (row0 + rl0 < M)
                    *(float2*)(km + (size_t)(row0 + rl0) * DIM + c0) =
                        make_float2(acc[mt][nt][0] + b0, acc[mt][nt][1] + b1);
                if (row0 + rl1 < M)
                    *(float2*)(km + (size_t)(row0 + rl1) * DIM + c0) =
                        make_float2(acc[mt][nt][2] + b0, acc[mt][nt][3] + b1);
            }
        }
    }
}

// ---------------------------------------------------------------------------
// EDGE: out += sum_e relu(tanh(gather@U0^T+b0)@U1^T+b1) . km[src] + kb[src]
__global__ void __launch_bounds__(NTHR, 1)
k_edge(const int* __restrict__ src, const int* __restrict__ dst,
       const float* __restrict__ P1, const float* __restrict__ P2,
       const float* __restrict__ U0W, const float* __restrict__ U0b,
       const float* __restrict__ U1W, const float* __restrict__ U1b,
       const float* __restrict__ km, const float* __restrict__ kb,
       float* __restrict__ out, int M) {
    extern __shared__ float sm[];
    float *B1 = sm + F_B1, *B2 = sm + F_B2, *KBs = sm + F_KB, *RED = sm + F_RED;
    float *W1 = sm + F_W1, *W2 = sm + F_W2, *As = sm + F_AS;
    const int tid = threadIdx.x;
    if (tid < 128) { B1[tid] = __ldg(U0b + tid); B2[tid] = __ldg(U1b + tid); }
    load_W(W1, U0W, tid);
    load_W(W2, U1W, tid);

    const int wid = tid >> 5, lane = tid & 31;
    const int gr = lane >> 2, tg = lane & 3;
    const int R0 = (wid >> 2) * 32, C0 = (wid & 3) * 32;
    const int mb0 = (wid >> 2) * 2, nb0 = (wid & 3) * 4;
    const int tiles = (M + 127) >> 7;
    float part = 0.f;

    for (int tile = blockIdx.x; tile < tiles; tile += gridDim.x) {
        const int row0 = tile << 7;
        __syncthreads();
        load_A_gather(As, src, dst, P1, P2, row0, M, tid);
        __syncthreads();
        float acc[2][4][4];
        ZERO_ACC(acc);
        gemm128(As, W1, acc, mb0, nb0, lane);
        __syncthreads();
        // t1 = tanh(acc + b1) -> As fragment layout
#pragma unroll
        for (int mt = 0; mt < 2; mt++) {
            int rl0 = R0 + mt * 16 + gr;
#pragma unroll
            for (int nt = 0; nt < 4; nt++) {
                int c0 = C0 + nt * 8 + 2 * tg;
                float b0 = B1[c0], b1 = B1[c0 + 1];
                int base = a_addr(rl0, c0);
                As[base + 0] = tf32r(tanhf(acc[mt][nt][0] + b0));
                As[base + 4] = tf32r(tanhf(acc[mt][nt][1] + b1));
                As[base + 1] = tf32r(tanhf(acc[mt][nt][2] + b0));
                As[base + 5] = tf32r(tanhf(acc[mt][nt][3] + b1));
            }
        }
        __syncthreads();
        ZERO_ACC(acc);
        gemm128(As, W2, acc, mb0, nb0, lane);
        __syncthreads();
        // stage km[src[row]] rows (row-major scratch) + kb[src[row]]
#pragma unroll
        for (int i = 0; i < 8; i++) {
            int idx = i * NTHR + tid;
            int r = idx >> 5, q = idx & 31;
            int row = row0 + r;
            float4 v = make_float4(0.f, 0.f, 0.f, 0.f);
            if (row < M)
                v = *(const float4*)(km + (size_t)__ldg(src + row) * DIM + q * 4);
            *(float4*)(As + r * A_BS + q * 4) = v;
        }
        if (tid < 128) {
            int row = row0 + tid;
            KBs[tid] = (row < M) ? __ldg(kb + __ldg(src + row)) : 0.f;
        }
        __syncthreads();
#pragma unroll
        for (int mt = 0; mt < 2; mt++) {
            int rl0 = R0 + mt * 16 + gr, rl1 = rl0 + 8;
            if (C0 == 0 && tg == 0) part += KBs[rl0] + KBs[rl1];
#pragma unroll
            for (int nt = 0; nt < 4; nt++) {
                int c0 = C0 + nt * 8 + 2 * tg;
                float b0 = B2[c0], b1 = B2[c0 + 1];
                float2 k0 = *(const float2*)(As + rl0 * A_BS + c0);
                float2 k1 = *(const float2*)(As + rl1 * A_BS + c0);
                part = fmaf(fmaxf(acc[mt][nt][0] + b0, 0.f), k0.x, part);
                part = fmaf(fmaxf(acc[mt][nt][1] + b1, 0.f), k0.y, part);
                part = fmaf(fmaxf(acc[mt][nt][2] + b0, 0.f), k1.x, part);
                part = fmaf(fmaxf(acc[mt][nt][3] + b1, 0.f), k1.y, part);
            }
        }
    }
#pragma unroll
    for (int o = 16; o > 0; o >>= 1)
        part += __shfl_xor_sync(0xffffffffu, part, o);
    __syncthreads();
    if (lane == 0) RED[wid] = part;
    __syncthreads();
    if (tid == 0) {
        float s = 0.f;
#pragma unroll
        for (int w = 0; w < 16; w++) s += RED[w];
        atomicAdd(out, s);
    }
}

// ---------------------------------------------------------------------------
// prep: M = K2W^T U2W, bc = K2b@U2W, v = K2W^T U2b, c = K2b.U2b
__global__ void k_prep(const float* __restrict__ K2W, const float* __restrict__ K2b,
                       const float* __restrict__ U2W, const float* __restrict__ U2b) {
    __shared__ float sa[128];
    int b = blockIdx.x, t = threadIdx.x;
    if (b < 128) {
        sa[t] = K2W[t * DIM + b];
        __syncthreads();
        float s = 0.f;
        for (int k = 0; k < 128; k++) s = fmaf(sa[k], U2W[k * DIM + t], s);
        g_M[b * DIM + t] = s;
    } else if (b == 128) {
        sa[t] = K2b[t];
        __syncthreads();
        float s = 0.f;
        for (int k = 0; k < 128; k++) s = fmaf(sa[k], U2W[k * DIM + t], s);
        g_bc[t] = s;
    } else {
        float s = 0.f;
        for (int k = 0; k < 128; k++) s = fmaf(K2W[k * DIM + t], U2b[k], s);
        g_v[t] = s;
        if (t == 0) {
            float cv = 0.f;
            for (int k = 0; k < 128; k++) cv = fmaf(K2b[k], U2b[k], cv);
            g_c[0] = cv;
        }
    }
}

__global__ void zero_kernel(float* __restrict__ out) {
    int i = blockIdx.x * blockDim.x + threadIdx.x;
    if (i < N_NODES * DIM) g_agg[i] = 0.0f;
    if (i == 0) out[0] = 0.0f;
}

// scatter with vector atomics: one red per float4
__global__ void scatter_kernel(const float* __restrict__ h1,
                               const int* __restrict__ src,
                               const int* __restrict__ dst) {
    int idx = blockIdx.x * blockDim.x + threadIdx.x;
    int e = idx >> 5;
    int q = (idx & 31) << 2;
    if (e < N_EDGES) {
        int s = __ldg(src + e);
        int d = __ldg(dst + e);
        float4 v = *(const float4*)(h1 + (size_t)s * DIM + q);
        atomicAdd((float4*)(g_agg + (size_t)d * DIM + q), v);
    }
}

// ---------------------------------------------------------------------------
extern "C" void kernel_launch(void* const* d_in, const int* in_sizes, int n_in,
                              void* d_out, int out_size) {
    const float* x      = (const float*)d_in[0];
    const int*   src    = (const int*)d_in[1];
    const int*   dst    = (const int*)d_in[2];
    const float* WencK  = (const float*)d_in[3];
    const float* bencK  = (const float*)d_in[4];
    const float* WencP1 = (const float*)d_in[5];
    const float* bencP1 = (const float*)d_in[6];
    const float* WencP2 = (const float*)d_in[7];
    const float* bencP2 = (const float*)d_in[8];
    const float* K0W = (const float*)d_in[9];
    const float* K0b = (const float*)d_in[10];
    const float* K1W = (const float*)d_in[11];
    const float* K1b = (const float*)d_in[12];
    const float* K2W = (const float*)d_in[13];
    const float* K2b = (const float*)d_in[14];
    const float* U0W = (const float*)d_in[15];
    const float* U0b = (const float*)d_in[16];
    const float* U1W = (const float*)d_in[17];
    const float* U1b = (const float*)d_in[18];
    const float* U2W = (const float*)d_in[19];
    const float* U2b = (const float*)d_in[20];
    float* out = (float*)d_out;

    float *h1, *p1, *p2, *agg, *t, *km, *kb, *Mw, *bc, *vv, *cc;
    cudaGetSymbolAddress((void**)&h1, g_h1);
    cudaGetSymbolAddress((void**)&p1, g_p1);
    cudaGetSymbolAddress((void**)&p2, g_p2);
    cudaGetSymbolAddress((void**)&agg, g_agg);
    cudaGetSymbolAddress((void**)&t, g_t);
    cudaGetSymbolAddress((void**)&km, g_km);
    cudaGetSymbolAddress((void**)&kb, g_kb);
    cudaGetSymbolAddress((void**)&Mw, g_M);
    cudaGetSymbolAddress((void**)&bc, g_bc);
    cudaGetSymbolAddress((void**)&vv, g_v);
    cudaGetSymbolAddress((void**)&cc, g_c);

    cudaFuncSetAttribute(k_single<0>, cudaFuncAttributeMaxDynamicSharedMemorySize, SMEM_TOTAL);
    cudaFuncSetAttribute(k_single<1>, cudaFuncAttributeMaxDynamicSharedMemorySize, SMEM_TOTAL);
    cudaFuncSetAttribute(k_dual, cudaFuncAttributeMaxDynamicSharedMemorySize, SMEM_TOTAL);
    cudaFuncSetAttribute(k_nodechain, cudaFuncAttributeMaxDynamicSharedMemorySize, SMEM_TOTAL);
    cudaFuncSetAttribute(k_edge, cudaFuncAttributeMaxDynamicSharedMemorySize, SMEM_TOTAL);

    dim3 blk(NTHR);

    zero_kernel<<<(N_NODES * DIM + 255) / 256, 256>>>(out);
    k_prep<<<130, 128>>>(K2W, K2b, U2W, U2b);

    // encoders
    k_single<0><<<GRID_P, blk, SMEM_TOTAL>>>(x, WencK, bencK, h1, N_NODES);
    k_dual<<<GRID_P, blk, SMEM_TOTAL>>>(x, WencP1, bencP1, WencP2, bencP2,
                                        p1, p2, N_NODES);

    // segment sum
    scatter_kernel<<<(N_EDGES * 32 + 255) / 256, 256>>>(h1, src, dst);

    // node MLP head + fused tail
    k_single<1><<<GRID_P, blk, SMEM_TOTAL>>>(agg, K0W, K0b, t, N_NODES);
    k_nodechain<<<GRID_P, blk, SMEM_TOTAL>>>(t, K1W, K1b, Mw, bc, vv, cc,
                                             km, kb, N_NODES);

    // fully fused edge pipeline
    k_edge<<<GRID_P, blk, SMEM_TOTAL>>>(src, dst, p1, p2, U0W, U0b, U1W, U1b,
                                        km, kb, out, N_EDGES);
}

// round 6
// speedup vs baseline: 1.3898x; 1.3898x over previous
#include <cuda_runtime.h>
#include <cstdint>
#include <math.h>

// ---------------------------------------------------------------------------
// Energy_Layer via tf32 mma.sync (m16n8k8).
//  Linearity fusion: U0(p1[s]+p2[d]) = q1[s]+q2[d], q_i = x@(U0W WencPi)^T (+bias)
//  Tail fusion:      dot(U2 h + b2, kn) folded into km/kb per node.
//  edge: out += sum_e relu(tanh(q1[s]+q2[d])@U1^T + b1) . km[s] + kb[s]
//  node: t = tanh(agg@K0^T+K0b); h2 = relu(t@K1^T+K1b); km = h2@M+bc; kb = h2.v+c
// Single-W GEMMs: M=64 tiles, 256 thr, 2 CTAs/SM. nodechain: M=128, 512 thr.
// ---------------------------------------------------------------------------

#define N_NODES 50000
#define N_EDGES 500000
#define DIM     128
#define NCTA_S  304
#define GRID_P  152

#define AS_STRIDE 132
#define WS_STRIDE 136

// --- config S smem (floats): single W, 64-row A tile, 256 threads ---
#define S_B1  0
#define S_B2  128
#define S_RED 256
#define S_W1  288
#define S_AS  (S_W1 + 128 * WS_STRIDE)
#define SMEM_S ((S_AS + 64 * AS_STRIDE) * 4)          // 104576 B -> 2 CTA/SM

// --- nodechain smem (floats): dual W, 128-row A tile, 512 threads ---
#define F_B1  0
#define F_B2  128
#define F_V   256
#define F_KB  384
#define F_RED 512
#define F_W1  544
#define F_W2  (F_W1 + 128 * WS_STRIDE)
#define F_AS  (F_W2 + 128 * WS_STRIDE)
#define SMEM_TOTAL ((F_AS + 128 * AS_STRIDE) * 4)     // 209024 B

// device scratch
__device__ float g_h1[(size_t)N_NODES * DIM];
__device__ float g_q1[(size_t)N_NODES * DIM];
__device__ float g_q2[(size_t)N_NODES * DIM];
__device__ float g_agg[(size_t)N_NODES * DIM];
__device__ float g_t[(size_t)N_NODES * DIM];
__device__ float g_km[(size_t)N_NODES * DIM];
__device__ float g_kb[N_NODES];
__device__ float g_M[DIM * DIM];
__device__ float g_A1[DIM * DIM];
__device__ float g_A2[DIM * DIM];
__device__ float g_bc[DIM];
__device__ float g_v[DIM];
__device__ float g_c[1];
__device__ float g_bq1[DIM];
__device__ float g_zero[DIM];        // stays zero (never written)

// ---------------------------------------------------------------------------
__device__ __forceinline__ float tf32r(float x) {
    uint32_t u;
    asm("cvt.rna.tf32.f32 %0, %1;" : "=r"(u) : "f"(x));
    return __uint_as_float(u);
}
__device__ __forceinline__ float tanha(float x) {
    float y;
    asm("tanh.approx.f32 %0, %1;" : "=f"(y) : "f"(x));
    return y;
}
__device__ __forceinline__ void mma_tf32(float* c4, uint32_t a0, uint32_t a1,
                                         uint32_t a2, uint32_t a3,
                                         uint32_t b0, uint32_t b1) {
    asm volatile(
        "mma.sync.aligned.m16n8k8.row.col.f32.tf32.tf32.f32 "
        "{%0,%1,%2,%3},{%4,%5,%6,%7},{%8,%9},{%0,%1,%2,%3};"
        : "+f"(c4[0]), "+f"(c4[1]), "+f"(c4[2]), "+f"(c4[3])
        : "r"(a0), "r"(a1), "r"(a2), "r"(a3), "r"(b0), "r"(b1));
}

// shared inner GEMM (R4-proven): warp tile 32x32 (mt=2, nt=4)
__device__ __forceinline__ void gemm_tile(const float* As, const float* Ws,
                                          float acc[2][4][4], int R0, int C0,
                                          int gr, int tg) {
#pragma unroll 8
    for (int kk = 0; kk < 16; kk++) {
        const int k0 = kk * 8;
        uint32_t a[2][4];
#pragma unroll
        for (int mt = 0; mt < 2; mt++) {
            const float* p = As + (R0 + mt * 16 + gr) * AS_STRIDE + k0 + tg;
            a[mt][0] = __float_as_uint(p[0]);
            a[mt][1] = __float_as_uint(p[8 * AS_STRIDE]);
            a[mt][2] = __float_as_uint(p[4]);
            a[mt][3] = __float_as_uint(p[8 * AS_STRIDE + 4]);
        }
#pragma unroll
        for (int nt = 0; nt < 4; nt++) {
            const float* q = Ws + (k0 + tg) * WS_STRIDE + C0 + nt * 8 + gr;
            uint32_t b0 = __float_as_uint(q[0]);
            uint32_t b1 = __float_as_uint(q[4 * WS_STRIDE]);
#pragma unroll
            for (int mt = 0; mt < 2; mt++)
                mma_tf32(acc[mt][nt], a[mt][0], a[mt][1], a[mt][2], a[mt][3],
                         b0, b1);
        }
    }
}

#define ZERO_ACC(acc)                                   \
    _Pragma("unroll") for (int _m = 0; _m < 2; _m++)    \
    _Pragma("unroll") for (int _n = 0; _n < 4; _n++)    \
    _Pragma("unroll") for (int _j = 0; _j < 4; _j++) acc[_m][_n][_j] = 0.f;

// ---------------------------------------------------------------------------
// config S loaders (256 threads)
// W^T loader: lanes span n (conflict-free STS); column-major LDG (L2-cached)
__device__ __forceinline__ void load_W_s(float* Ws, const float* __restrict__ W,
                                         int tid) {
#pragma unroll
    for (int i = 0; i < 16; i++) {
        int pos = i * 256 + tid;
        int n = pos & 127, kq = pos >> 7;         // k = kq*4 + j
        float4 w = *(const float4*)(W + n * DIM + kq * 4);
#pragma unroll
        for (int j = 0; j < 4; j++)
            Ws[(kq * 4 + j) * WS_STRIDE + n] =
                tf32r(j == 0 ? w.x : j == 1 ? w.y : j == 2 ? w.z : w.w);
    }
}

__device__ __forceinline__ void load_A_s(float* As, const float* __restrict__ A,
                                         int row0, int M, int tid) {
#pragma unroll
    for (int i = 0; i < 8; i++) {
        int idx = i * 256 + tid;
        int r = idx >> 5, q = idx & 31;
        int row = row0 + r;
        float4 v = make_float4(0.f, 0.f, 0.f, 0.f);
        if (row < M) v = *(const float4*)(A + (size_t)row * DIM + q * 4);
        float4 o = make_float4(tf32r(v.x), tf32r(v.y), tf32r(v.z), tf32r(v.w));
        *(float4*)(As + r * AS_STRIDE + q * 4) = o;
    }
}

// ---------------------------------------------------------------------------
// SINGLE gemm (config S): C = act(A@W^T + b)   ACT: 0 none, 1 tanh
template <int ACT>
__global__ void __launch_bounds__(256, 2)
k_single_s(const float* __restrict__ A, const float* __restrict__ W,
           const float* __restrict__ bias, float* __restrict__ C, int M) {
    extern __shared__ float sm[];
    float *B1 = sm + S_B1, *W1 = sm + S_W1, *As = sm + S_AS;
    const int tid = threadIdx.x;
    if (tid < 128) B1[tid] = __ldg(bias + tid);
    load_W_s(W1, W, tid);

    const int wid = tid >> 5, lane = tid & 31;
    const int gr = lane >> 2, tg = lane & 3;
    const int R0 = (wid >> 2) * 32, C0 = (wid & 3) * 32;
    const int tiles = (M + 63) >> 6;

    for (int tile = blockIdx.x; tile < tiles; tile += gridDim.x) {
        const int row0 = tile << 6;
        __syncthreads();
        load_A_s(As, A, row0, M, tid);
        __syncthreads();
        float acc[2][4][4];
        ZERO_ACC(acc);
        gemm_tile(As, W1, acc, R0, C0, gr, tg);
#pragma unroll
        for (int mt = 0; mt < 2; mt++) {
            int rl0 = R0 + mt * 16 + gr, rl1 = rl0 + 8;
#pragma unroll
            for (int nt = 0; nt < 4; nt++) {
                int c0 = C0 + nt * 8 + 2 * tg;
                float b0 = B1[c0], b1 = B1[c0 + 1];
                float v00 = acc[mt][nt][0] + b0, v01 = acc[mt][nt][1] + b1;
                float v10 = acc[mt][nt][2] + b0, v11 = acc[mt][nt][3] + b1;
                if (ACT == 1) { v00 = tanhf(v00); v01 = tanhf(v01);
                                v10 = tanhf(v10); v11 = tanhf(v11); }
                if (row0 + rl0 < M)
                    *(float2*)(C + (size_t)(row0 + rl0) * DIM + c0) =
                        make_float2(v00, v01);
                if (row0 + rl1 < M)
                    *(float2*)(C + (size_t)(row0 + rl1) * DIM + c0) =
                        make_float2(v10, v11);
            }
        }
    }
}

// ---------------------------------------------------------------------------
// EDGE (config S): out += sum_e relu(tanh(q1[s]+q2[d])@U1^T + b1).km[s] + kb[s]
__global__ void __launch_bounds__(256, 2)
k_edge_s(const int* __restrict__ src, const int* __restrict__ dst,
         const float* __restrict__ Q1, const float* __restrict__ Q2,
         const float* __restrict__ U1W, const float* __restrict__ U1b,
         const float* __restrict__ km, const float* __restrict__ kb,
         float* __restrict__ out, int M) {
    extern __shared__ float sm[];
    float *B2 = sm + S_B2, *RED = sm + S_RED, *W1 = sm + S_W1, *As = sm + S_AS;
    const int tid = threadIdx.x;
    if (tid < 128) B2[tid] = __ldg(U1b + tid);
    load_W_s(W1, U1W, tid);

    const int wid = tid >> 5, lane = tid & 31;
    const int gr = lane >> 2, tg = lane & 3;
    const int R0 = (wid >> 2) * 32, C0 = (wid & 3) * 32;
    const int tiles = (M + 63) >> 6;
    float part = 0.f;

    for (int tile = blockIdx.x; tile < tiles; tile += gridDim.x) {
        const int row0 = tile << 6;
        __syncthreads();
        // load: tanh(q1[src]+q2[dst]) -> As
#pragma unroll
        for (int i = 0; i < 8; i++) {
            int idx = i * 256 + tid;
            int r = idx >> 5, q = idx & 31;
            int row = row0 + r;
            float4 v = make_float4(0.f, 0.f, 0.f, 0.f);
            if (row < M) {
                int s = __ldg(src + row);
                int d = __ldg(dst + row);
                float4 a = *(const float4*)(Q1 + (size_t)s * DIM + q * 4);
                float4 b = *(const float4*)(Q2 + (size_t)d * DIM + q * 4);
                v = make_float4(tanha(a.x + b.x), tanha(a.y + b.y),
                                tanha(a.z + b.z), tanha(a.w + b.w));
            }
            float4 o = make_float4(tf32r(v.x), tf32r(v.y), tf32r(v.z),
                                   tf32r(v.w));
            *(float4*)(As + r * AS_STRIDE + q * 4) = o;
        }
        __syncthreads();
        float acc[2][4][4];
        ZERO_ACC(acc);
        gemm_tile(As, W1, acc, R0, C0, gr, tg);
        // dot epilogue: direct global km/kb loads (L2-resident)
#pragma unroll
        for (int mt = 0; mt < 2; mt++) {
            int r0g = row0 + R0 + mt * 16 + gr, r1g = r0g + 8;
            bool v0 = r0g < M, v1 = r1g < M;
            int s0 = v0 ? __ldg(src + r0g) : 0;
            int s1 = v1 ? __ldg(src + r1g) : 0;
            if (C0 == 0 && tg == 0) {
                if (v0) part += __ldg(kb + s0);
                if (v1) part += __ldg(kb + s1);
            }
            const float* km0 = km + (size_t)s0 * DIM;
            const float* km1 = km + (size_t)s1 * DIM;
#pragma unroll
            for (int nt = 0; nt < 4; nt++) {
                int c0 = C0 + nt * 8 + 2 * tg;
                float b0 = B2[c0], b1 = B2[c0 + 1];
                float2 k0 = v0 ? *(const float2*)(km0 + c0)
                               : make_float2(0.f, 0.f);
                float2 k1 = v1 ? *(const float2*)(km1 + c0)
                               : make_float2(0.f, 0.f);
                part = fmaf(fmaxf(acc[mt][nt][0] + b0, 0.f), k0.x, part);
                part = fmaf(fmaxf(acc[mt][nt][1] + b1, 0.f), k0.y, part);
                part = fmaf(fmaxf(acc[mt][nt][2] + b0, 0.f), k1.x, part);
                part = fmaf(fmaxf(acc[mt][nt][3] + b1, 0.f), k1.y, part);
            }
        }
    }
#pragma unroll
    for (int o = 16; o > 0; o >>= 1)
        part += __shfl_xor_sync(0xffffffffu, part, o);
    __syncthreads();
    if (lane == 0) RED[wid] = part;
    __syncthreads();
    if (tid == 0) {
        float s = 0.f;
#pragma unroll
        for (int w = 0; w < 8; w++) s += RED[w];
        atomicAdd(out, s);
    }
}

// ---------------------------------------------------------------------------
// nodechain loaders (512 threads, R4-proven)
__device__ __forceinline__ void load_W_512(float* Ws, float* As,
                                           const float* __restrict__ W, int tid) {
#pragma unroll
    for (int i = 0; i < 8; i++) {
        int idx = i * 512 + tid;
        int n = idx >> 5, q = idx & 31;
        float4 w = *(const float4*)(W + n * DIM + q * 4);
        float4 o = make_float4(tf32r(w.x), tf32r(w.y), tf32r(w.z), tf32r(w.w));
        *(float4*)(As + n * AS_STRIDE + q * 4) = o;
    }
    __syncthreads();
#pragma unroll
    for (int i = 0; i < 8; i++) {
        int idx = i * 512 + tid;
        int n = idx & 127, kq = idx >> 7;
#pragma unroll
        for (int j = 0; j < 4; j++)
            Ws[(4 * kq + j) * WS_STRIDE + n] = As[n * AS_STRIDE + 4 * kq + j];
    }
    __syncthreads();
}
__device__ __forceinline__ void load_W_rows_512(float* Ws,
                                                const float* __restrict__ W,
                                                int tid) {
#pragma unroll
    for (int i = 0; i < 8; i++) {
        int idx = i * 512 + tid;
        int k = idx >> 5, q = idx & 31;
        float4 w = *(const float4*)(W + k * DIM + q * 4);
        float4 o = make_float4(tf32r(w.x), tf32r(w.y), tf32r(w.z), tf32r(w.w));
        *(float4*)(Ws + k * WS_STRIDE + q * 4) = o;
    }
    __syncthreads();
}
__device__ __forceinline__ void load_A_512(float* As, const float* __restrict__ A,
                                           int row0, int M, int tid) {
#pragma unroll
    for (int i = 0; i < 8; i++) {
        int idx = i * 512 + tid;
        int r = idx >> 5, q = idx & 31;
        int row = row0 + r;
        float4 v = make_float4(0.f, 0.f, 0.f, 0.f);
        if (row < M) v = *(const float4*)(A + (size_t)row * DIM + q * 4);
        float4 o = make_float4(tf32r(v.x), tf32r(v.y), tf32r(v.z), tf32r(v.w));
        *(float4*)(As + r * AS_STRIDE + q * 4) = o;
    }
}

// NODECHAIN:  h2 = relu(t@K1^T + K1b);  km = h2@M + bc;  kb = h2.v + c
__global__ void __launch_bounds__(512, 1)
k_nodechain(const float* __restrict__ T, const float* __restrict__ K1W,
            const float* __restrict__ K1b, const float* __restrict__ Mw,
            const float* __restrict__ bc, const float* __restrict__ vv,
            const float* __restrict__ cc, float* __restrict__ km,
            float* __restrict__ kb, int M) {
    extern __shared__ float sm[];
    float *B1 = sm + F_B1, *B2 = sm + F_B2, *V = sm + F_V;
    float *W1 = sm + F_W1, *W2 = sm + F_W2, *As = sm + F_AS;
    const int tid = threadIdx.x;
    if (tid < 128) { B1[tid] = __ldg(K1b + tid); B2[tid] = __ldg(bc + tid);
                     V[tid] = __ldg(vv + tid); }
    const float cval = __ldg(cc);
    load_W_512(W1, As, K1W, tid);
    load_W_rows_512(W2, Mw, tid);

    const int wid = tid >> 5, lane = tid & 31;
    const int gr = lane >> 2, tg = lane & 3;
    const int R0 = (wid >> 2) * 32, C0 = (wid & 3) * 32;
    const int tiles = (M + 127) >> 7;

    for (int tile = blockIdx.x; tile < tiles; tile += gridDim.x) {
        const int row0 = tile << 7;
        __syncthreads();
        load_A_512(As, T, row0, M, tid);
        __syncthreads();
        float acc[2][4][4];
        ZERO_ACC(acc);
        gemm_tile(As, W1, acc, R0, C0, gr, tg);
        __syncthreads();
        // h2 = relu(acc + b1) -> As (tf32)
#pragma unroll
        for (int mt = 0; mt < 2; mt++) {
            int rl0 = R0 + mt * 16 + gr, rl1 = rl0 + 8;
#pragma unroll
            for (int nt = 0; nt < 4; nt++) {
                int c0 = C0 + nt * 8 + 2 * tg;
                float b0 = B1[c0], b1 = B1[c0 + 1];
                *(float2*)(As + rl0 * AS_STRIDE + c0) = make_float2(
                    tf32r(fmaxf(acc[mt][nt][0] + b0, 0.f)),
                    tf32r(fmaxf(acc[mt][nt][1] + b1, 0.f)));
                *(float2*)(As + rl1 * AS_STRIDE + c0) = make_float2(
                    tf32r(fmaxf(acc[mt][nt][2] + b0, 0.f)),
                    tf32r(fmaxf(acc[mt][nt][3] + b1, 0.f)));
            }
        }
        __syncthreads();
        // kb = h2.v + c   (4 threads per row)
        {
            int r = tid >> 2, qt = tid & 3;
            const float* hp = As + r * AS_STRIDE + qt * 32;
            float s = 0.f;
#pragma unroll
            for (int j = 0; j < 32; j++) s = fmaf(hp[j], V[qt * 32 + j], s);
            s += __shfl_xor_sync(0xffffffffu, s, 1);
            s += __shfl_xor_sync(0xffffffffu, s, 2);
            if (qt == 0 && row0 + r < M) kb[row0 + r] = s + cval;
        }
        // km = h2 @ M + bc
        ZERO_ACC(acc);
        gemm_tile(As, W2, acc, R0, C0, gr, tg);
#pragma unroll
        for (int mt = 0; mt < 2; mt++) {
            int rl0 = R0 + mt * 16 + gr, rl1 = rl0 + 8;
#pragma unroll
            for (int nt = 0; nt < 4; nt++) {
                int c0 = C0 + nt * 8 + 2 * tg;
                float b0 = B2[c0], b1 = B2[c0 + 1];
                if (row0 + rl0 < M)
                    *(float2*)(km + (size_t)(row0 + rl0) * DIM + c0) =
                        make_float2(acc[mt][nt][0] + b0, acc[mt][nt][1] + b1);
                if (row0 + rl1 < M)
                    *(float2*)(km + (size_t)(row0 + rl1) * DIM + c0) =
                        make_float2(acc[mt][nt][2] + b0, acc[mt][nt][3] + b1);
            }
        }
    }
}

// ---------------------------------------------------------------------------
// prep: g_M = K2W^T U2W, g_bc = K2b@U2W, g_v = K2W^T U2b, g_c = K2b.U2b,
//       g_A1 = U0W@WencP1, g_A2 = U0W@WencP2, g_bq1 = U0W@(bP1+bP2)+U0b
__global__ void k_prep(const float* __restrict__ K2W, const float* __restrict__ K2b,
                       const float* __restrict__ U2W, const float* __restrict__ U2b,
                       const float* __restrict__ U0W, const float* __restrict__ U0b,
                       const float* __restrict__ WencP1,
                       const float* __restrict__ bencP1,
                       const float* __restrict__ WencP2,
                       const float* __restrict__ bencP2) {
    __shared__ float sa[128];
    int b = blockIdx.x, t = threadIdx.x;
    if (b < 128) {                       // g_M row b
        sa[t] = K2W[t * DIM + b];
        __syncthreads();
        float s = 0.f;
        for (int k = 0; k < 128; k++) s = fmaf(sa[k], U2W[k * DIM + t], s);
        g_M[b * DIM + t] = s;
    } else if (b < 256) {                // g_A1 row r = U0W[r,:] @ WencP1
        int r = b - 128;
        sa[t] = U0W[r * DIM + t];
        __syncthreads();
        float s = 0.f;
        for (int k = 0; k < 128; k++) s = fmaf(sa[k], WencP1[k * DIM + t], s);
        g_A1[r * DIM + t] = s;
    } else if (b < 384) {                // g_A2 row
        int r = b - 256;
        sa[t] = U0W[r * DIM + t];
        __syncthreads();
        float s = 0.f;
        for (int k = 0; k < 128; k++) s = fmaf(sa[k], WencP2[k * DIM + t], s);
        g_A2[r * DIM + t] = s;
    } else if (b == 384) {               // g_bc
        sa[t] = K2b[t];
        __syncthreads();
        float s = 0.f;
        for (int k = 0; k < 128; k++) s = fmaf(sa[k], U2W[k * DIM + t], s);
        g_bc[t] = s;
    } else if (b == 385) {               // g_v, g_c
        float s = 0.f;
        for (int k = 0; k < 128; k++) s = fmaf(K2W[k * DIM + t], U2b[k], s);
        g_v[t] = s;
        if (t == 0) {
            float cv = 0.f;
            for (int k = 0; k < 128; k++) cv = fmaf(K2b[k], U2b[k], cv);
            g_c[0] = cv;
        }
    } else {                             // g_bq1
        sa[t] = __ldg(bencP1 + t) + __ldg(bencP2 + t);
        __syncthreads();
        float s = 0.f;
        for (int k = 0; k < 128; k++) s = fmaf(U0W[t * DIM + k], sa[k], s);
        g_bq1[t] = s + __ldg(U0b + t);
    }
}

__global__ void zero_kernel(float* __restrict__ out) {
    int i = blockIdx.x * blockDim.x + threadIdx.x;
    if (i < N_NODES * DIM) g_agg[i] = 0.0f;
    if (i == 0) out[0] = 0.0f;
}

__global__ void scatter_kernel(const float* __restrict__ h1,
                               const int* __restrict__ src,
                               const int* __restrict__ dst) {
    int idx = blockIdx.x * blockDim.x + threadIdx.x;
    int e = idx >> 5;
    int q = (idx & 31) << 2;
    if (e < N_EDGES) {
        int s = __ldg(src + e);
        int d = __ldg(dst + e);
        float4 v = *(const float4*)(h1 + (size_t)s * DIM + q);
        atomicAdd((float4*)(g_agg + (size_t)d * DIM + q), v);
    }
}

// ---------------------------------------------------------------------------
extern "C" void kernel_launch(void* const* d_in, const int* in_sizes, int n_in,
                              void* d_out, int out_size) {
    const float* x      = (const float*)d_in[0];
    const int*   src    = (const int*)d_in[1];
    const int*   dst    = (const int*)d_in[2];
    const float* WencK  = (const float*)d_in[3];
    const float* bencK  = (const float*)d_in[4];
    const float* WencP1 = (const float*)d_in[5];
    const float* bencP1 = (const float*)d_in[6];
    const float* WencP2 = (const float*)d_in[7];
    const float* bencP2 = (const float*)d_in[8];
    const float* K0W = (const float*)d_in[9];
    const float* K0b = (const float*)d_in[10];
    const float* K1W = (const float*)d_in[11];
    const float* K1b = (const float*)d_in[12];
    const float* K2W = (const float*)d_in[13];
    const float* K2b = (const float*)d_in[14];
    const float* U0W = (const float*)d_in[15];
    const float* U0b = (const float*)d_in[16];
    const float* U1W = (const float*)d_in[17];
    const float* U1b = (const float*)d_in[18];
    const float* U2W = (const float*)d_in[19];
    const float* U2b = (const float*)d_in[20];
    float* out = (float*)d_out;

    float *h1, *q1, *q2, *agg, *t, *km, *kb, *Mw, *A1, *A2, *bc, *vv, *cc,
          *bq1, *zz;
    cudaGetSymbolAddress((void**)&h1, g_h1);
    cudaGetSymbolAddress((void**)&q1, g_q1);
    cudaGetSymbolAddress((void**)&q2, g_q2);
    cudaGetSymbolAddress((void**)&agg, g_agg);
    cudaGetSymbolAddress((void**)&t, g_t);
    cudaGetSymbolAddress((void**)&km, g_km);
    cudaGetSymbolAddress((void**)&kb, g_kb);
    cudaGetSymbolAddress((void**)&Mw, g_M);
    cudaGetSymbolAddress((void**)&A1, g_A1);
    cudaGetSymbolAddress((void**)&A2, g_A2);
    cudaGetSymbolAddress((void**)&bc, g_bc);
    cudaGetSymbolAddress((void**)&vv, g_v);
    cudaGetSymbolAddress((void**)&cc, g_c);
    cudaGetSymbolAddress((void**)&bq1, g_bq1);
    cudaGetSymbolAddress((void**)&zz, g_zero);

    cudaFuncSetAttribute(k_single_s<0>, cudaFuncAttributeMaxDynamicSharedMemorySize, SMEM_S);
    cudaFuncSetAttribute(k_single_s<1>, cudaFuncAttributeMaxDynamicSharedMemorySize, SMEM_S);
    cudaFuncSetAttribute(k_edge_s, cudaFuncAttributeMaxDynamicSharedMemorySize, SMEM_S);
    cudaFuncSetAttribute(k_nodechain, cudaFuncAttributeMaxDynamicSharedMemorySize, SMEM_TOTAL);

    zero_kernel<<<(N_NODES * DIM + 255) / 256, 256>>>(out);
    k_prep<<<387, 128>>>(K2W, K2b, U2W, U2b, U0W, U0b, WencP1, bencP1,
                         WencP2, bencP2);

    // encoders (q1/q2 use prep-fused weights)
    k_single_s<0><<<NCTA_S, 256, SMEM_S>>>(x, WencK, bencK, h1, N_NODES);
    k_single_s<0><<<NCTA_S, 256, SMEM_S>>>(x, A1, bq1, q1, N_NODES);
    k_single_s<0><<<NCTA_S, 256, SMEM_S>>>(x, A2, zz, q2, N_NODES);

    // segment sum
    scatter_kernel<<<(N_EDGES * 32 + 255) / 256, 256>>>(h1, src, dst);

    // node MLP head + fused tail
    k_single_s<1><<<NCTA_S, 256, SMEM_S>>>(agg, K0W, K0b, t, N_NODES);
    k_nodechain<<<GRID_P, 512, SMEM_TOTAL>>>(t, K1W, K1b, Mw, bc, vv, cc,
                                             km, kb, N_NODES);

    // fused edge pipeline (single GEMM)
    k_edge_s<<<NCTA_S, 256, SMEM_S>>>(src, dst, q1, q2, U1W, U1b, km, kb,
                                      out, N_EDGES);
}

// round 7
// speedup vs baseline: 1.5116x; 1.0876x over previous
#include <cuda_runtime.h>
#include <cstdint>
#include <math.h>

// ---------------------------------------------------------------------------
// Energy_Layer via tf32 mma.sync (m16n8k8), full algebraic fusion.
//  scatter:  xs = segsum(x[src] -> dst), indeg, outdeg
//  node:     t  = tanh(xs@B^T + indeg*u + K0b)         B = K0W@WencK, u = K0W@bencK
//            h2 = relu(t@K1^T+K1b); km = h2@M+bc; kb = h2.v+c   (M = K2W^T U2W ...)
//  kb fold:  out += sum_n outdeg[n]*kb[n]
//  edge:     out += sum_e relu(tanh(q1[s]+q2[d])@U1^T + b1) . km[s]
//            q1 = x@(U0W WencP1)^T + bq1,  q2 = x@(U0W WencP2)^T
// ---------------------------------------------------------------------------

#define N_NODES 50000
#define N_EDGES 500000
#define DIM     128
#define NCTA_S  304
#define GRID_P  152

#define AS_STRIDE 132
#define WS_STRIDE 136

// --- config S smem (floats): single W, 64-row A tile, 256 threads ---
#define S_B1  0
#define S_B2  128
#define S_RED 256
#define S_W1  288
#define S_AS  (S_W1 + 128 * WS_STRIDE)
#define SMEM_S ((S_AS + 64 * AS_STRIDE) * 4)          // 104576 B -> 2 CTA/SM

// --- 512-thr smem (floats): dual W, 128-row A tile ---
#define F_B1  0
#define F_B2  128
#define F_V   256
#define F_KB  384
#define F_RED 512
#define F_W1  544
#define F_W2  (F_W1 + 128 * WS_STRIDE)
#define F_AS  (F_W2 + 128 * WS_STRIDE)
#define SMEM_TOTAL ((F_AS + 128 * AS_STRIDE) * 4)     // 209024 B

// device scratch
__device__ float g_q1[(size_t)N_NODES * DIM];
__device__ float g_q2[(size_t)N_NODES * DIM];
__device__ float g_agg[(size_t)N_NODES * DIM];
__device__ float g_t[(size_t)N_NODES * DIM];
__device__ float g_km[(size_t)N_NODES * DIM];
__device__ float g_kb[N_NODES];
__device__ float g_deg[N_NODES];      // in-degree
__device__ float g_odeg[N_NODES];     // out-degree
__device__ float g_M[DIM * DIM];
__device__ float g_A1[DIM * DIM];
__device__ float g_A2[DIM * DIM];
__device__ float g_B[DIM * DIM];
__device__ float g_bc[DIM];
__device__ float g_v[DIM];
__device__ float g_c[1];
__device__ float g_bq1[DIM];
__device__ float g_u[DIM];
__device__ float g_zero[DIM];         // stays zero (never written)

// ---------------------------------------------------------------------------
__device__ __forceinline__ float tf32r(float x) {
    uint32_t u;
    asm("cvt.rna.tf32.f32 %0, %1;" : "=r"(u) : "f"(x));
    return __uint_as_float(u);
}
__device__ __forceinline__ float tanha(float x) {
    float y;
    asm("tanh.approx.f32 %0, %1;" : "=f"(y) : "f"(x));
    return y;
}
__device__ __forceinline__ void mma_tf32(float* c4, uint32_t a0, uint32_t a1,
                                         uint32_t a2, uint32_t a3,
                                         uint32_t b0, uint32_t b1) {
    asm volatile(
        "mma.sync.aligned.m16n8k8.row.col.f32.tf32.tf32.f32 "
        "{%0,%1,%2,%3},{%4,%5,%6,%7},{%8,%9},{%0,%1,%2,%3};"
        : "+f"(c4[0]), "+f"(c4[1]), "+f"(c4[2]), "+f"(c4[3])
        : "r"(a0), "r"(a1), "r"(a2), "r"(a3), "r"(b0), "r"(b1));
}

// shared inner GEMM (R4/R6-proven): warp tile 32x32 (mt=2, nt=4)
__device__ __forceinline__ void gemm_tile(const float* As, const float* Ws,
                                          float acc[2][4][4], int R0, int C0,
                                          int gr, int tg) {
#pragma unroll 8
    for (int kk = 0; kk < 16; kk++) {
        const int k0 = kk * 8;
        uint32_t a[2][4];
#pragma unroll
        for (int mt = 0; mt < 2; mt++) {
            const float* p = As + (R0 + mt * 16 + gr) * AS_STRIDE + k0 + tg;
            a[mt][0] = __float_as_uint(p[0]);
            a[mt][1] = __float_as_uint(p[8 * AS_STRIDE]);
            a[mt][2] = __float_as_uint(p[4]);
            a[mt][3] = __float_as_uint(p[8 * AS_STRIDE + 4]);
        }
#pragma unroll
        for (int nt = 0; nt < 4; nt++) {
            const float* q = Ws + (k0 + tg) * WS_STRIDE + C0 + nt * 8 + gr;
            uint32_t b0 = __float_as_uint(q[0]);
            uint32_t b1 = __float_as_uint(q[4 * WS_STRIDE]);
#pragma unroll
            for (int mt = 0; mt < 2; mt++)
                mma_tf32(acc[mt][nt], a[mt][0], a[mt][1], a[mt][2], a[mt][3],
                         b0, b1);
        }
    }
}

#define ZERO_ACC(acc)                                   \
    _Pragma("unroll") for (int _m = 0; _m < 2; _m++)    \
    _Pragma("unroll") for (int _n = 0; _n < 4; _n++)    \
    _Pragma("unroll") for (int _j = 0; _j < 4; _j++) acc[_m][_n][_j] = 0.f;

// ---------------------------------------------------------------------------
// config S loaders (256 threads)
__device__ __forceinline__ void load_W_s(float* Ws, const float* __restrict__ W,
                                         int tid) {
#pragma unroll
    for (int i = 0; i < 16; i++) {
        int pos = i * 256 + tid;
        int n = pos & 127, kq = pos >> 7;
        float4 w = *(const float4*)(W + n * DIM + kq * 4);
#pragma unroll
        for (int j = 0; j < 4; j++)
            Ws[(kq * 4 + j) * WS_STRIDE + n] =
                tf32r(j == 0 ? w.x : j == 1 ? w.y : j == 2 ? w.z : w.w);
    }
}

__device__ __forceinline__ void load_A_s(float* As, const float* __restrict__ A,
                                         int row0, int M, int tid) {
#pragma unroll
    for (int i = 0; i < 8; i++) {
        int idx = i * 256 + tid;
        int r = idx >> 5, q = idx & 31;
        int row = row0 + r;
        float4 v = make_float4(0.f, 0.f, 0.f, 0.f);
        if (row < M) v = *(const float4*)(A + (size_t)row * DIM + q * 4);
        float4 o = make_float4(tf32r(v.x), tf32r(v.y), tf32r(v.z), tf32r(v.w));
        *(float4*)(As + r * AS_STRIDE + q * 4) = o;
    }
}

// ---------------------------------------------------------------------------
// FUSED K-encoder (config S): t = tanh(xs@B^T + deg[r]*u + K0b)
__global__ void __launch_bounds__(256, 2)
k_fusedK(const float* __restrict__ XS, const float* __restrict__ B,
         const float* __restrict__ uu, const float* __restrict__ K0b,
         const float* __restrict__ deg, float* __restrict__ C, int M) {
    extern __shared__ float sm[];
    float *B1 = sm + S_B1, *B2 = sm + S_B2, *W1 = sm + S_W1, *As = sm + S_AS;
    const int tid = threadIdx.x;
    if (tid < 128) { B1[tid] = __ldg(K0b + tid); B2[tid] = __ldg(uu + tid); }
    load_W_s(W1, B, tid);

    const int wid = tid >> 5, lane = tid & 31;
    const int gr = lane >> 2, tg = lane & 3;
    const int R0 = (wid >> 2) * 32, C0 = (wid & 3) * 32;
    const int tiles = (M + 63) >> 6;

    for (int tile = blockIdx.x; tile < tiles; tile += gridDim.x) {
        const int row0 = tile << 6;
        __syncthreads();
        load_A_s(As, XS, row0, M, tid);
        __syncthreads();
        float acc[2][4][4];
        ZERO_ACC(acc);
        gemm_tile(As, W1, acc, R0, C0, gr, tg);
#pragma unroll
        for (int mt = 0; mt < 2; mt++) {
            int rl0 = R0 + mt * 16 + gr, rl1 = rl0 + 8;
            int g0 = row0 + rl0, g1 = row0 + rl1;
            float d0 = (g0 < M) ? __ldg(deg + g0) : 0.f;
            float d1 = (g1 < M) ? __ldg(deg + g1) : 0.f;
#pragma unroll
            for (int nt = 0; nt < 4; nt++) {
                int c0 = C0 + nt * 8 + 2 * tg;
                float b0 = B1[c0], b1 = B1[c0 + 1];
                float u0 = B2[c0], u1 = B2[c0 + 1];
                float v00 = tanhf(fmaf(d0, u0, acc[mt][nt][0] + b0));
                float v01 = tanhf(fmaf(d0, u1, acc[mt][nt][1] + b1));
                float v10 = tanhf(fmaf(d1, u0, acc[mt][nt][2] + b0));
                float v11 = tanhf(fmaf(d1, u1, acc[mt][nt][3] + b1));
                if (g0 < M)
                    *(float2*)(C + (size_t)g0 * DIM + c0) = make_float2(v00, v01);
                if (g1 < M)
                    *(float2*)(C + (size_t)g1 * DIM + c0) = make_float2(v10, v11);
            }
        }
    }
}

// ---------------------------------------------------------------------------
// EDGE (config S): out += sum_e relu(tanh(q1[s]+q2[d])@U1^T + b1).km[s]
__global__ void __launch_bounds__(256, 2)
k_edge_s(const int* __restrict__ src, const int* __restrict__ dst,
         const float* __restrict__ Q1, const float* __restrict__ Q2,
         const float* __restrict__ U1W, const float* __restrict__ U1b,
         const float* __restrict__ km, float* __restrict__ out, int M) {
    extern __shared__ float sm[];
    float *B2 = sm + S_B2, *RED = sm + S_RED, *W1 = sm + S_W1, *As = sm + S_AS;
    const int tid = threadIdx.x;
    if (tid < 128) B2[tid] = __ldg(U1b + tid);
    load_W_s(W1, U1W, tid);

    const int wid = tid >> 5, lane = tid & 31;
    const int gr = lane >> 2, tg = lane & 3;
    const int R0 = (wid >> 2) * 32, C0 = (wid & 3) * 32;
    const int tiles = (M + 63) >> 6;
    float part = 0.f;

    for (int tile = blockIdx.x; tile < tiles; tile += gridDim.x) {
        const int row0 = tile << 6;
        __syncthreads();
#pragma unroll
        for (int i = 0; i < 8; i++) {
            int idx = i * 256 + tid;
            int r = idx >> 5, q = idx & 31;
            int row = row0 + r;
            float4 v = make_float4(0.f, 0.f, 0.f, 0.f);
            if (row < M) {
                int s = __ldg(src + row);
                int d = __ldg(dst + row);
                float4 a = *(const float4*)(Q1 + (size_t)s * DIM + q * 4);
                float4 b = *(const float4*)(Q2 + (size_t)d * DIM + q * 4);
                v = make_float4(tanha(a.x + b.x), tanha(a.y + b.y),
                                tanha(a.z + b.z), tanha(a.w + b.w));
            }
            float4 o = make_float4(tf32r(v.x), tf32r(v.y), tf32r(v.z),
                                   tf32r(v.w));
            *(float4*)(As + r * AS_STRIDE + q * 4) = o;
        }
        __syncthreads();
        float acc[2][4][4];
        ZERO_ACC(acc);
        gemm_tile(As, W1, acc, R0, C0, gr, tg);
#pragma unroll
        for (int mt = 0; mt < 2; mt++) {
            int r0g = row0 + R0 + mt * 16 + gr, r1g = r0g + 8;
            bool v0 = r0g < M, v1 = r1g < M;
            int s0 = v0 ? __ldg(src + r0g) : 0;
            int s1 = v1 ? __ldg(src + r1g) : 0;
            const float* km0 = km + (size_t)s0 * DIM;
            const float* km1 = km + (size_t)s1 * DIM;
#pragma unroll
            for (int nt = 0; nt < 4; nt++) {
                int c0 = C0 + nt * 8 + 2 * tg;
                float b0 = B2[c0], b1 = B2[c0 + 1];
                float2 k0 = v0 ? *(const float2*)(km0 + c0)
                               : make_float2(0.f, 0.f);
                float2 k1 = v1 ? *(const float2*)(km1 + c0)
                               : make_float2(0.f, 0.f);
                part = fmaf(fmaxf(acc[mt][nt][0] + b0, 0.f), k0.x, part);
                part = fmaf(fmaxf(acc[mt][nt][1] + b1, 0.f), k0.y, part);
                part = fmaf(fmaxf(acc[mt][nt][2] + b0, 0.f), k1.x, part);
                part = fmaf(fmaxf(acc[mt][nt][3] + b1, 0.f), k1.y, part);
            }
        }
    }
#pragma unroll
    for (int o = 16; o > 0; o >>= 1)
        part += __shfl_xor_sync(0xffffffffu, part, o);
    __syncthreads();
    if (lane == 0) RED[wid] = part;
    __syncthreads();
    if (tid == 0) {
        float s = 0.f;
#pragma unroll
        for (int w = 0; w < 8; w++) s += RED[w];
        atomicAdd(out, s);
    }
}

// ---------------------------------------------------------------------------
// 512-thread loaders (R4/R6-proven)
__device__ __forceinline__ void load_W_512(float* Ws, float* As,
                                           const float* __restrict__ W, int tid) {
#pragma unroll
    for (int i = 0; i < 8; i++) {
        int idx = i * 512 + tid;
        int n = idx >> 5, q = idx & 31;
        float4 w = *(const float4*)(W + n * DIM + q * 4);
        float4 o = make_float4(tf32r(w.x), tf32r(w.y), tf32r(w.z), tf32r(w.w));
        *(float4*)(As + n * AS_STRIDE + q * 4) = o;
    }
    __syncthreads();
#pragma unroll
    for (int i = 0; i < 8; i++) {
        int idx = i * 512 + tid;
        int n = idx & 127, kq = idx >> 7;
#pragma unroll
        for (int j = 0; j < 4; j++)
            Ws[(4 * kq + j) * WS_STRIDE + n] = As[n * AS_STRIDE + 4 * kq + j];
    }
    __syncthreads();
}
__device__ __forceinline__ void load_W_rows_512(float* Ws,
                                                const float* __restrict__ W,
                                                int tid) {
#pragma unroll
    for (int i = 0; i < 8; i++) {
        int idx = i * 512 + tid;
        int k = idx >> 5, q = idx & 31;
        float4 w = *(const float4*)(W + k * DIM + q * 4);
        float4 o = make_float4(tf32r(w.x), tf32r(w.y), tf32r(w.z), tf32r(w.w));
        *(float4*)(Ws + k * WS_STRIDE + q * 4) = o;
    }
    __syncthreads();
}
__device__ __forceinline__ void load_A_512(float* As, const float* __restrict__ A,
                                           int row0, int M, int tid) {
#pragma unroll
    for (int i = 0; i < 8; i++) {
        int idx = i * 512 + tid;
        int r = idx >> 5, q = idx & 31;
        int row = row0 + r;
        float4 v = make_float4(0.f, 0.f, 0.f, 0.f);
        if (row < M) v = *(const float4*)(A + (size_t)row * DIM + q * 4);
        float4 o = make_float4(tf32r(v.x), tf32r(v.y), tf32r(v.z), tf32r(v.w));
        *(float4*)(As + r * AS_STRIDE + q * 4) = o;
    }
}

// DUAL gemm (R4-proven): C1 = A@Wa^T + ba ; C2 = A@Wb^T + bb
__global__ void __launch_bounds__(512, 1)
k_dual(const float* __restrict__ A, const float* __restrict__ Wa,
       const float* __restrict__ ba, const float* __restrict__ Wb,
       const float* __restrict__ bb, float* __restrict__ C1,
       float* __restrict__ C2, int M) {
    extern __shared__ float sm[];
    float *B1 = sm + F_B1, *B2 = sm + F_B2;
    float *W1 = sm + F_W1, *W2 = sm + F_W2, *As = sm + F_AS;
    const int tid = threadIdx.x;
    if (tid < 128) { B1[tid] = __ldg(ba + tid); B2[tid] = __ldg(bb + tid); }
    load_W_512(W1, As, Wa, tid);
    load_W_512(W2, As, Wb, tid);

    const int wid = tid >> 5, lane = tid & 31;
    const int gr = lane >> 2, tg = lane & 3;
    const int R0 = (wid >> 2) * 32, C0 = (wid & 3) * 32;
    const int tiles = (M + 127) >> 7;

    for (int tile = blockIdx.x; tile < tiles; tile += gridDim.x) {
        const int row0 = tile << 7;
        __syncthreads();
        load_A_512(As, A, row0, M, tid);
        __syncthreads();
#pragma unroll
        for (int pass = 0; pass < 2; pass++) {
            const float* Ws = pass ? W2 : W1;
            const float* Bs = pass ? B2 : B1;
            float* C = pass ? C2 : C1;
            float acc[2][4][4];
            ZERO_ACC(acc);
            gemm_tile(As, Ws, acc, R0, C0, gr, tg);
#pragma unroll
            for (int mt = 0; mt < 2; mt++) {
                int rl0 = R0 + mt * 16 + gr, rl1 = rl0 + 8;
#pragma unroll
                for (int nt = 0; nt < 4; nt++) {
                    int c0 = C0 + nt * 8 + 2 * tg;
                    float b0 = Bs[c0], b1 = Bs[c0 + 1];
                    if (row0 + rl0 < M)
                        *(float2*)(C + (size_t)(row0 + rl0) * DIM + c0) =
                            make_float2(acc[mt][nt][0] + b0, acc[mt][nt][1] + b1);
                    if (row0 + rl1 < M)
                        *(float2*)(C + (size_t)(row0 + rl1) * DIM + c0) =
                            make_float2(acc[mt][nt][2] + b0, acc[mt][nt][3] + b1);
                }
            }
        }
    }
}

// NODECHAIN (R6-proven): h2 = relu(t@K1^T+K1b); km = h2@M+bc; kb = h2.v+c
__global__ void __launch_bounds__(512, 1)
k_nodechain(const float* __restrict__ T, const float* __restrict__ K1W,
            const float* __restrict__ K1b, const float* __restrict__ Mw,
            const float* __restrict__ bc, const float* __restrict__ vv,
            const float* __restrict__ cc, float* __restrict__ km,
            float* __restrict__ kb, int M) {
    extern __shared__ float sm[];
    float *B1 = sm + F_B1, *B2 = sm + F_B2, *V = sm + F_V;
    float *W1 = sm + F_W1, *W2 = sm + F_W2, *As = sm + F_AS;
    const int tid = threadIdx.x;
    if (tid < 128) { B1[tid] = __ldg(K1b + tid); B2[tid] = __ldg(bc + tid);
                     V[tid] = __ldg(vv + tid); }
    const float cval = __ldg(cc);
    load_W_512(W1, As, K1W, tid);
    load_W_rows_512(W2, Mw, tid);

    const int wid = tid >> 5, lane = tid & 31;
    const int gr = lane >> 2, tg = lane & 3;
    const int R0 = (wid >> 2) * 32, C0 = (wid & 3) * 32;
    const int tiles = (M + 127) >> 7;

    for (int tile = blockIdx.x; tile < tiles; tile += gridDim.x) {
        const int row0 = tile << 7;
        __syncthreads();
        load_A_512(As, T, row0, M, tid);
        __syncthreads();
        float acc[2][4][4];
        ZERO_ACC(acc);
        gemm_tile(As, W1, acc, R0, C0, gr, tg);
        __syncthreads();
#pragma unroll
        for (int mt = 0; mt < 2; mt++) {
            int rl0 = R0 + mt * 16 + gr, rl1 = rl0 + 8;
#pragma unroll
            for (int nt = 0; nt < 4; nt++) {
                int c0 = C0 + nt * 8 + 2 * tg;
                float b0 = B1[c0], b1 = B1[c0 + 1];
                *(float2*)(As + rl0 * AS_STRIDE + c0) = make_float2(
                    tf32r(fmaxf(acc[mt][nt][0] + b0, 0.f)),
                    tf32r(fmaxf(acc[mt][nt][1] + b1, 0.f)));
                *(float2*)(As + rl1 * AS_STRIDE + c0) = make_float2(
                    tf32r(fmaxf(acc[mt][nt][2] + b0, 0.f)),
                    tf32r(fmaxf(acc[mt][nt][3] + b1, 0.f)));
            }
        }
        __syncthreads();
        {
            int r = tid >> 2, qt = tid & 3;
            const float* hp = As + r * AS_STRIDE + qt * 32;
            float s = 0.f;
#pragma unroll
            for (int j = 0; j < 32; j++) s = fmaf(hp[j], V[qt * 32 + j], s);
            s += __shfl_xor_sync(0xffffffffu, s, 1);
            s += __shfl_xor_sync(0xffffffffu, s, 2);
            if (qt == 0 && row0 + r < M) kb[row0 + r] = s + cval;
        }
        ZERO_ACC(acc);
        gemm_tile(As, W2, acc, R0, C0, gr, tg);
#pragma unroll
        for (int mt = 0; mt < 2; mt++) {
            int rl0 = R0 + mt * 16 + gr, rl1 = rl0 + 8;
#pragma unroll
            for (int nt = 0; nt < 4; nt++) {
                int c0 = C0 + nt * 8 + 2 * tg;
                float b0 = B2[c0], b1 = B2[c0 + 1];
                if (row0 + rl0 < M)
                    *(float2*)(km + (size_t)(row0 + rl0) * DIM + c0) =
                        make_float2(acc[mt][nt][0] + b0, acc[mt][nt][1] + b1);
                if (row0 + rl1 < M)
                    *(float2*)(km + (size_t)(row0 + rl1) * DIM + c0) =
                        make_float2(acc[mt][nt][2] + b0, acc[mt][nt][3] + b1);
            }
        }
    }
}

// ---------------------------------------------------------------------------
// prep: g_M=K2W^T U2W, g_A1=U0W@WencP1, g_A2=U0W@WencP2, g_B=K0W@WencK,
//       g_bc=K2b@U2W, g_v=K2W^T U2b, g_c=K2b.U2b, g_bq1=U0W@(bP1+bP2)+U0b,
//       g_u=K0W@bencK
__global__ void k_prep(const float* __restrict__ K2W, const float* __restrict__ K2b,
                       const float* __restrict__ U2W, const float* __restrict__ U2b,
                       const float* __restrict__ U0W, const float* __restrict__ U0b,
                       const float* __restrict__ WencP1,
                       const float* __restrict__ bencP1,
                       const float* __restrict__ WencP2,
                       const float* __restrict__ bencP2,
                       const float* __restrict__ K0W,
                       const float* __restrict__ WencK,
                       const float* __restrict__ bencK) {
    __shared__ float sa[128];
    int b = blockIdx.x, t = threadIdx.x;
    if (b < 128) {
        sa[t] = K2W[t * DIM + b];
        __syncthreads();
        float s = 0.f;
        for (int k = 0; k < 128; k++) s = fmaf(sa[k], U2W[k * DIM + t], s);
        g_M[b * DIM + t] = s;
    } else if (b < 256) {
        int r = b - 128;
        sa[t] = U0W[r * DIM + t];
        __syncthreads();
        float s = 0.f;
        for (int k = 0; k < 128; k++) s = fmaf(sa[k], WencP1[k * DIM + t], s);
        g_A1[r * DIM + t] = s;
    } else if (b < 384) {
        int r = b - 256;
        sa[t] = U0W[r * DIM + t];
        __syncthreads();
        float s = 0.f;
        for (int k = 0; k < 128; k++) s = fmaf(sa[k], WencP2[k * DIM + t], s);
        g_A2[r * DIM + t] = s;
    } else if (b < 512) {
        int r = b - 384;
        sa[t] = K0W[r * DIM + t];
        __syncthreads();
        float s = 0.f;
        for (int k = 0; k < 128; k++) s = fmaf(sa[k], WencK[k * DIM + t], s);
        g_B[r * DIM + t] = s;
    } else if (b == 512) {
        sa[t] = K2b[t];
        __syncthreads();
        float s = 0.f;
        for (int k = 0; k < 128; k++) s = fmaf(sa[k], U2W[k * DIM + t], s);
        g_bc[t] = s;
    } else if (b == 513) {
        float s = 0.f;
        for (int k = 0; k < 128; k++) s = fmaf(K2W[k * DIM + t], U2b[k], s);
        g_v[t] = s;
        if (t == 0) {
            float cv = 0.f;
            for (int k = 0; k < 128; k++) cv = fmaf(K2b[k], U2b[k], cv);
            g_c[0] = cv;
        }
    } else if (b == 514) {
        sa[t] = __ldg(bencP1 + t) + __ldg(bencP2 + t);
        __syncthreads();
        float s = 0.f;
        for (int k = 0; k < 128; k++) s = fmaf(U0W[t * DIM + k], sa[k], s);
        g_bq1[t] = s + __ldg(U0b + t);
    } else {
        float s = 0.f;
        for (int k = 0; k < 128; k++) s = fmaf(K0W[t * DIM + k], __ldg(bencK + k), s);
        g_u[t] = s;
    }
}

__global__ void zero_kernel(float* __restrict__ out) {
    int i = blockIdx.x * blockDim.x + threadIdx.x;
    if (i < N_NODES * DIM) g_agg[i] = 0.0f;
    if (i < N_NODES) { g_deg[i] = 0.0f; g_odeg[i] = 0.0f; }
    if (i == 0) out[0] = 0.0f;
}

// scatter x rows + degree counts
__global__ void scatter_kernel(const float* __restrict__ x,
                               const int* __restrict__ src,
                               const int* __restrict__ dst) {
    int idx = blockIdx.x * blockDim.x + threadIdx.x;
    int e = idx >> 5;
    int q = (idx & 31) << 2;
    if (e < N_EDGES) {
        int s = __ldg(src + e);
        int d = __ldg(dst + e);
        float4 v = *(const float4*)(x + (size_t)s * DIM + q);
        atomicAdd((float4*)(g_agg + (size_t)d * DIM + q), v);
        if (q == 0) {
            atomicAdd(g_deg + d, 1.0f);
            atomicAdd(g_odeg + s, 1.0f);
        }
    }
}

// out += sum_n odeg[n]*kb[n]
__global__ void k_kbdot(const float* __restrict__ kb,
                        const float* __restrict__ odeg,
                        float* __restrict__ out) {
    __shared__ float red[8];
    int i = blockIdx.x * 256 + threadIdx.x;
    float p = (i < N_NODES) ? kb[i] * odeg[i] : 0.f;
#pragma unroll
    for (int o = 16; o > 0; o >>= 1)
        p += __shfl_xor_sync(0xffffffffu, p, o);
    int lane = threadIdx.x & 31, wid = threadIdx.x >> 5;
    if (lane == 0) red[wid] = p;
    __syncthreads();
    if (threadIdx.x == 0) {
        float s = 0.f;
#pragma unroll
        for (int w = 0; w < 8; w++) s += red[w];
        atomicAdd(out, s);
    }
}

// ---------------------------------------------------------------------------
extern "C" void kernel_launch(void* const* d_in, const int* in_sizes, int n_in,
                              void* d_out, int out_size) {
    const float* x      = (const float*)d_in[0];
    const int*   src    = (const int*)d_in[1];
    const int*   dst    = (const int*)d_in[2];
    const float* WencK  = (const float*)d_in[3];
    const float* bencK  = (const float*)d_in[4];
    const float* WencP1 = (const float*)d_in[5];
    const float* bencP1 = (const float*)d_in[6];
    const float* WencP2 = (const float*)d_in[7];
    const float* bencP2 = (const float*)d_in[8];
    const float* K0W = (const float*)d_in[9];
    const float* K0b = (const float*)d_in[10];
    const float* K1W = (const float*)d_in[11];
    const float* K1b = (const float*)d_in[12];
    const float* K2W = (const float*)d_in[13];
    const float* K2b = (const float*)d_in[14];
    const float* U0W = (const float*)d_in[15];
    const float* U0b = (const float*)d_in[16];
    const float* U1W = (const float*)d_in[17];
    const float* U1b = (const float*)d_in[18];
    const float* U2W = (const float*)d_in[19];
    const float* U2b = (const float*)d_in[20];
    float* out = (float*)d_out;

    float *q1, *q2, *agg, *t, *km, *kb, *deg, *odeg, *Mw, *A1, *A2, *Bw,
          *bc, *vv, *cc, *bq1, *uu, *zz;
    cudaGetSymbolAddress((void**)&q1, g_q1);
    cudaGetSymbolAddress((void**)&q2, g_q2);
    cudaGetSymbolAddress((void**)&agg, g_agg);
    cudaGetSymbolAddress((void**)&t, g_t);
    cudaGetSymbolAddress((void**)&km, g_km);
    cudaGetSymbolAddress((void**)&kb, g_kb);
    cudaGetSymbolAddress((void**)&deg, g_deg);
    cudaGetSymbolAddress((void**)&odeg, g_odeg);
    cudaGetSymbolAddress((void**)&Mw, g_M);
    cudaGetSymbolAddress((void**)&A1, g_A1);
    cudaGetSymbolAddress((void**)&A2, g_A2);
    cudaGetSymbolAddress((void**)&Bw, g_B);
    cudaGetSymbolAddress((void**)&bc, g_bc);
    cudaGetSymbolAddress((void**)&vv, g_v);
    cudaGetSymbolAddress((void**)&cc, g_c);
    cudaGetSymbolAddress((void**)&bq1, g_bq1);
    cudaGetSymbolAddress((void**)&uu, g_u);
    cudaGetSymbolAddress((void**)&zz, g_zero);

    cudaFuncSetAttribute(k_fusedK, cudaFuncAttributeMaxDynamicSharedMemorySize, SMEM_S);
    cudaFuncSetAttribute(k_edge_s, cudaFuncAttributeMaxDynamicSharedMemorySize, SMEM_S);
    cudaFuncSetAttribute(k_dual, cudaFuncAttributeMaxDynamicSharedMemorySize, SMEM_TOTAL);
    cudaFuncSetAttribute(k_nodechain, cudaFuncAttributeMaxDynamicSharedMemorySize, SMEM_TOTAL);

    zero_kernel<<<(N_NODES * DIM + 255) / 256, 256>>>(out);
    k_prep<<<516, 128>>>(K2W, K2b, U2W, U2b, U0W, U0b, WencP1, bencP1,
                         WencP2, bencP2, K0W, WencK, bencK);

    // xs = segsum(x), degree counts
    scatter_kernel<<<(N_EDGES * 32 + 255) / 256, 256>>>(x, src, dst);

    // node chain: t = tanh(xs@B^T + deg*u + K0b); then km/kb
    k_fusedK<<<NCTA_S, 256, SMEM_S>>>(agg, Bw, uu, K0b, deg, t, N_NODES);
    k_nodechain<<<GRID_P, 512, SMEM_TOTAL>>>(t, K1W, K1b, Mw, bc, vv, cc,
                                             km, kb, N_NODES);
    k_kbdot<<<(N_NODES + 255) / 256, 256>>>(kb, odeg, out);

    // q1/q2 via shared-A dual GEMM
    k_dual<<<GRID_P, 512, SMEM_TOTAL>>>(x, A1, bq1, A2, zz, q1, q2, N_NODES);

    // fused edge pipeline
    k_edge_s<<<NCTA_S, 256, SMEM_S>>>(src, dst, q1, q2, U1W, U1b, km, out,
                                      N_EDGES);
}